// round 11
// baseline (speedup 1.0000x reference)
#include <cuda_runtime.h>
#include <cuda_fp16.h>
#include <cstdint>

// GlobalAggregator: B=256, N=256, K=16, DIM=128
// Block-cooperative tile of 8 bn (M=128 rows). B (w1^T fp16) fragments persistent in
// registers per warp (16-e strip, loaded ONCE). Gated A (fp16) staged in SMEM per tile,
// read via ldmatrix. Cross-warp partial reduction for the w2 dot; softmax+output warp-local.

#define DIMX 128
#define KN   16
#define TBN  8
#define NTHREADS 256
#define ASTRIDE 272          // bytes per row (128 fp16 + 8 pad) -> conflict-free ldmatrix

#define SM_AB   0            // 128 x 272 = 34816 (Bt during init, then A tiles)
#define SM_PART 34816        // 8 x 128 f32 = 4096
#define SM_WTS  38912        // 128 f32 (nweight rows of tile)
#define SM_BIAS 39424        // 128 f32
#define SM_W2   39936        // 128 f32
#define SM_TOTAL 40448

static __device__ __forceinline__ uint32_t smem_u32(const void* p) {
    uint32_t a;
    asm("{ .reg .u64 t; cvta.to.shared.u64 t, %1; cvt.u32.u64 %0, t; }" : "=r"(a) : "l"(p));
    return a;
}
static __device__ __forceinline__ void ldsm4(uint32_t& r0, uint32_t& r1, uint32_t& r2, uint32_t& r3,
                                             uint32_t addr) {
    asm volatile("ldmatrix.sync.aligned.m8n8.x4.shared.b16 {%0,%1,%2,%3}, [%4];"
                 : "=r"(r0), "=r"(r1), "=r"(r2), "=r"(r3) : "r"(addr));
}
static __device__ __forceinline__ void mma_f16(float& c0, float& c1, float& c2, float& c3,
                                               uint32_t a0, uint32_t a1, uint32_t a2, uint32_t a3,
                                               uint32_t b0, uint32_t b1) {
    asm volatile("mma.sync.aligned.m16n8k16.row.col.f32.f16.f16.f32 "
                 "{%0,%1,%2,%3},{%4,%5,%6,%7},{%8,%9},{%0,%1,%2,%3};"
                 : "+f"(c0), "+f"(c1), "+f"(c2), "+f"(c3)
                 : "r"(a0), "r"(a1), "r"(a2), "r"(a3), "r"(b0), "r"(b1));
}
static __device__ __forceinline__ uint32_t pack_h2(float x, float y) {
    __half2 h(__float2half_rn(x), __float2half_rn(y));
    return *(uint32_t*)&h;
}
__device__ __forceinline__ float leaky02(float v) { return v > 0.0f ? v : 0.2f * v; }

extern "C" __global__ void __launch_bounds__(NTHREADS, 2)
agg_mma_kernel(const float* __restrict__ neighbor,
               const float* __restrict__ nweight,
               const float* __restrict__ extra,
               const float* __restrict__ w1,
               const float* __restrict__ w2,
               float* __restrict__ out,
               int ntiles)
{
    extern __shared__ __align__(16) char smem[];
    const uint32_t sbase = smem_u32(smem);
    const int tid  = threadIdx.x;
    const int warp = tid >> 5;
    const int lane = tid & 31;

    float* part  = (float*)(smem + SM_PART);   // [8][128]
    float* wts   = (float*)(smem + SM_WTS);
    float* biass = (float*)(smem + SM_BIAS);
    float* w2s   = (float*)(smem + SM_W2);

    // ---- phase 0: build Bt (w1 transposed, fp16) in the AB region ----
    for (int idx = tid; idx < DIMX * DIMX; idx += NTHREADS) {
        int d = idx >> 7;          // reduction dim (w1 row)
        int e = idx & 127;         // output dim  (w1 col) -> Bt row
        *(__half*)(smem + SM_AB + (uint32_t)e * ASTRIDE + (uint32_t)d * 2) = __float2half_rn(w1[idx]);
    }
    if (tid < DIMX) {
        biass[tid] = w1[DIMX * DIMX + tid];
        w2s[tid]   = w2[tid];
    }
    __syncthreads();

    // ---- load persistent B frags: warp's 16-e strip, all 8 kc chunks (32 regs) ----
    uint32_t bb[8][4];
    {
        const uint32_t bfbase = sbase + SM_AB
            + (uint32_t)(warp * 16 + (lane & 7) + ((lane >> 4) & 1) * 8) * ASTRIDE
            + ((lane >> 3) & 1) * 16;
        #pragma unroll
        for (int kc = 0; kc < 8; ++kc)
            ldsm4(bb[kc][0], bb[kc][1], bb[kc][2], bb[kc][3], bfbase + kc * 32);
    }
    __syncthreads();   // Bt fully consumed; AB region becomes the A tile

    // A ldmatrix lane addressing (within a 16-row m-tile)
    const uint32_t afbase = sbase + SM_AB
        + (uint32_t)((lane & 7) + ((lane >> 3) & 1) * 8) * ASTRIDE
        + (lane >> 4) * 16;

    const int g  = lane >> 2;          // row group 0..7
    const int i2 = (lane & 3) * 2;     // col pair base
    const int e0 = warp * 16 + i2;     // warp's e-strip, n-tile 0
    const float b00 = biass[e0],     b01 = biass[e0 + 1];
    const float b10 = biass[e0 + 8], b11 = biass[e0 + 9];
    const float v00 = w2s[e0],       v01 = w2s[e0 + 1];
    const float v10 = w2s[e0 + 8],   v11 = w2s[e0 + 9];

    for (int tile = blockIdx.x; tile < ntiles; tile += gridDim.x) {
        const size_t bn0 = (size_t)tile * TBN;

        // ---- step 1: stage nweight + build gated A tile (fp16, ldsm layout) ----
        if (tid < 128) wts[tid] = nweight[bn0 * KN + tid];
        {
            const float4* nsrc = (const float4*)neighbor + (size_t)tile * 4096;
            const float4* esrc = (const float4*)extra + bn0 * 32;
            #pragma unroll
            for (int i = 0; i < 16; ++i) {
                int idx4 = tid + i * NTHREADS;      // 0..4095
                int m  = idx4 >> 5;                  // M row (bnl*16 + k)
                int q  = idx4 & 31;                  // float4 col index
                float4 nv = nsrc[idx4];
                float4 ev = __ldg(esrc + (m >> 4) * 32 + q);
                uint2 hv;
                hv.x = pack_h2(nv.x * ev.x, nv.y * ev.y);
                hv.y = pack_h2(nv.z * ev.z, nv.w * ev.w);
                *(uint2*)(smem + SM_AB + (uint32_t)m * ASTRIDE + (uint32_t)q * 8) = hv;
            }
        }
        __syncthreads();

        // ---- step 2: GEMM in two M-halves + partial epilogue ----
        #pragma unroll
        for (int half = 0; half < 2; ++half) {
            float c[4][2][4];
            #pragma unroll
            for (int mtl = 0; mtl < 4; ++mtl)
                #pragma unroll
                for (int nt = 0; nt < 2; ++nt)
                    { c[mtl][nt][0]=0.f; c[mtl][nt][1]=0.f; c[mtl][nt][2]=0.f; c[mtl][nt][3]=0.f; }

            #pragma unroll
            for (int kc = 0; kc < 8; ++kc) {
                #pragma unroll
                for (int mtl = 0; mtl < 4; ++mtl) {
                    const int mt = half * 4 + mtl;
                    uint32_t a0, a1, a2, a3;
                    ldsm4(a0, a1, a2, a3, afbase + (uint32_t)(mt * 16) * ASTRIDE + kc * 32);
                    mma_f16(c[mtl][0][0], c[mtl][0][1], c[mtl][0][2], c[mtl][0][3],
                            a0, a1, a2, a3, bb[kc][0], bb[kc][1]);
                    mma_f16(c[mtl][1][0], c[mtl][1][1], c[mtl][1][2], c[mtl][1][3],
                            a0, a1, a2, a3, bb[kc][2], bb[kc][3]);
                }
            }

            // partial w2-dot for this half's 64 M rows (warp's 16-e strip only)
            #pragma unroll
            for (int mtl = 0; mtl < 4; ++mtl) {
                const int mt = half * 4 + mtl;
                const float wk0 = wts[mt * 16 + g];
                const float wk1 = wts[mt * 16 + g + 8];
                float p0 = leaky02(c[mtl][0][0] + wk0 * b00) * v00
                         + leaky02(c[mtl][0][1] + wk0 * b01) * v01
                         + leaky02(c[mtl][1][0] + wk0 * b10) * v10
                         + leaky02(c[mtl][1][1] + wk0 * b11) * v11;
                float p1 = leaky02(c[mtl][0][2] + wk1 * b00) * v00
                         + leaky02(c[mtl][0][3] + wk1 * b01) * v01
                         + leaky02(c[mtl][1][2] + wk1 * b10) * v10
                         + leaky02(c[mtl][1][3] + wk1 * b11) * v11;
                p0 += __shfl_xor_sync(0xffffffffu, p0, 1);
                p0 += __shfl_xor_sync(0xffffffffu, p0, 2);
                p1 += __shfl_xor_sync(0xffffffffu, p1, 1);
                p1 += __shfl_xor_sync(0xffffffffu, p1, 2);
                if ((lane & 3) == 0) {
                    part[warp * 128 + mt * 16 + g]     = p0;
                    part[warp * 128 + mt * 16 + g + 8] = p1;
                }
            }
        }
        __syncthreads();

        // ---- step 3: warp w owns bn0+w — reduce partials, softmax, output ----
        {
            const int r = warp * 16 + (lane & 15);
            float s = 0.f;
            #pragma unroll
            for (int pw = 0; pw < 8; ++pw) s += part[pw * 128 + r];

            float mx = s;
            #pragma unroll
            for (int o = 8; o > 0; o >>= 1)
                mx = fmaxf(mx, __shfl_xor_sync(0xffffffffu, mx, o));
            float ev = __expf(s - mx);
            float es = ev;
            #pragma unroll
            for (int o = 8; o > 0; o >>= 1)
                es += __shfl_xor_sync(0xffffffffu, es, o);
            float alpha = ev / es;

            float al2[KN];
            #pragma unroll
            for (int k = 0; k < KN; ++k)
                al2[k] = __shfl_sync(0xffffffffu, alpha, k);

            const float* nbase = neighbor + (bn0 + warp) * (size_t)(KN * DIMX);
            const float4* nb4 = (const float4*)nbase + lane;
            float4 acc = make_float4(0.f, 0.f, 0.f, 0.f);
            #pragma unroll
            for (int k = 0; k < KN; ++k) {
                float4 nv = nb4[k * 32];
                acc.x = fmaf(al2[k], nv.x, acc.x);
                acc.y = fmaf(al2[k], nv.y, acc.y);
                acc.z = fmaf(al2[k], nv.z, acc.z);
                acc.w = fmaf(al2[k], nv.w, acc.w);
            }
            ((float4*)(out + (bn0 + warp) * DIMX))[lane] = acc;
        }
        __syncthreads();   // partials + A tile reused next iteration
    }
}

extern "C" void kernel_launch(void* const* d_in, const int* in_sizes, int n_in,
                              void* d_out, int out_size) {
    const float* neighbor = (const float*)d_in[1];
    const float* nweight  = (const float*)d_in[4];
    const float* extra    = (const float*)d_in[5];
    const float* w1       = (const float*)d_in[6];
    const float* w2       = (const float*)d_in[7];
    float* out            = (float*)d_out;

    const int total_bn = in_sizes[5] / DIMX;   // 65536
    const int ntiles   = total_bn / TBN;       // 8192

    cudaFuncSetAttribute(agg_mma_kernel, cudaFuncAttributeMaxDynamicSharedMemorySize, SM_TOTAL);
    agg_mma_kernel<<<304, NTHREADS, SM_TOTAL>>>(neighbor, nweight, extra, w1, w2, out, ntiles);
}

// round 12
// speedup vs baseline: 1.1205x; 1.1205x over previous
#include <cuda_runtime.h>
#include <cuda_fp16.h>
#include <cstdint>

// GlobalAggregator: B=256, N=256, K=16, DIM=128
// cp.async double-buffered pipeline. Tile = 4 bn (M=64 rows).
//  - B (w1^T fp16) fragments persistent in registers per warp (16-e strip, loaded once)
//  - raw neighbor/extra/nweight of tile t+1 streamed into SMEM via cp.async.cg while
//    tile t is gated->fp16-packed (A tile), GEMMed, and output
//  - output weighted-sum reads raw neighbor from SMEM (no global re-read)

#define DIMX 128
#define KN   16
#define TBN  4
#define MROWS 64
#define NTHREADS 256
#define ASTRIDE 272          // bytes per A/Bt row (128 fp16 + 8 pad)

#define SM_A     0           // 64 x 272 = 17408 (Bt spans here + RAW0 during init only)
#define SM_RAW0  17408       // 64x128 f32 = 32768
#define SM_RAW1  50176       // 32768
#define SM_EX    82944       // 2 x 512 f32 = 4096
#define SM_WT    87040       // 2 x 64 f32  = 512
#define SM_PART  87552       // 8 x 64 f32  = 2048
#define SM_BIAS  89600       // 128 f32
#define SM_W2    90112       // 128 f32
#define SM_TOTAL 90624

static __device__ __forceinline__ uint32_t smem_u32(const void* p) {
    uint32_t a;
    asm("{ .reg .u64 t; cvta.to.shared.u64 t, %1; cvt.u32.u64 %0, t; }" : "=r"(a) : "l"(p));
    return a;
}
static __device__ __forceinline__ void cp16(uint32_t saddr, const void* g) {
    asm volatile("cp.async.cg.shared.global [%0], [%1], 16;" :: "r"(saddr), "l"(g));
}
static __device__ __forceinline__ void cp_commit() {
    asm volatile("cp.async.commit_group;" ::: "memory");
}
static __device__ __forceinline__ void cp_wait0() {
    asm volatile("cp.async.wait_group 0;" ::: "memory");
}
static __device__ __forceinline__ void ldsm4(uint32_t& r0, uint32_t& r1, uint32_t& r2, uint32_t& r3,
                                             uint32_t addr) {
    asm volatile("ldmatrix.sync.aligned.m8n8.x4.shared.b16 {%0,%1,%2,%3}, [%4];"
                 : "=r"(r0), "=r"(r1), "=r"(r2), "=r"(r3) : "r"(addr));
}
static __device__ __forceinline__ void mma_f16(float& c0, float& c1, float& c2, float& c3,
                                               uint32_t a0, uint32_t a1, uint32_t a2, uint32_t a3,
                                               uint32_t b0, uint32_t b1) {
    asm volatile("mma.sync.aligned.m16n8k16.row.col.f32.f16.f16.f32 "
                 "{%0,%1,%2,%3},{%4,%5,%6,%7},{%8,%9},{%0,%1,%2,%3};"
                 : "+f"(c0), "+f"(c1), "+f"(c2), "+f"(c3)
                 : "r"(a0), "r"(a1), "r"(a2), "r"(a3), "r"(b0), "r"(b1));
}
static __device__ __forceinline__ uint32_t pack_h2(float x, float y) {
    __half2 h(__float2half_rn(x), __float2half_rn(y));
    return *(uint32_t*)&h;
}
__device__ __forceinline__ float leaky02(float v) { return v > 0.0f ? v : 0.2f * v; }

extern "C" __global__ void __launch_bounds__(NTHREADS, 2)
agg_mma_kernel(const float* __restrict__ neighbor,
               const float* __restrict__ nweight,
               const float* __restrict__ extra,
               const float* __restrict__ w1,
               const float* __restrict__ w2,
               float* __restrict__ out,
               int ntiles)
{
    extern __shared__ __align__(16) char smem[];
    const uint32_t sbase = smem_u32(smem);
    const int tid  = threadIdx.x;
    const int warp = tid >> 5;
    const int lane = tid & 31;

    float* part  = (float*)(smem + SM_PART);
    float* biass = (float*)(smem + SM_BIAS);
    float* w2s   = (float*)(smem + SM_W2);

    // ---- phase 0: build Bt (w1^T fp16) across SM_A+SM_RAW0 region (init only) ----
    for (int idx = tid; idx < DIMX * DIMX; idx += NTHREADS) {
        int d = idx >> 7;
        int e = idx & 127;
        *(__half*)(smem + (uint32_t)e * ASTRIDE + (uint32_t)d * 2) = __float2half_rn(w1[idx]);
    }
    if (tid < DIMX) {
        biass[tid] = w1[DIMX * DIMX + tid];
        w2s[tid]   = w2[tid];
    }
    __syncthreads();

    // ---- persistent B frags: warp's 16-e strip, 8 kc chunks (32 regs) ----
    uint32_t bb[8][4];
    {
        const uint32_t bfbase = sbase
            + (uint32_t)(warp * 16 + (lane & 7) + ((lane >> 4) & 1) * 8) * ASTRIDE
            + ((lane >> 3) & 1) * 16;
        #pragma unroll
        for (int kc = 0; kc < 8; ++kc)
            ldsm4(bb[kc][0], bb[kc][1], bb[kc][2], bb[kc][3], bfbase + kc * 32);
    }
    __syncthreads();   // Bt consumed; regions become A tile + raw buffers

    // ---- prologue: stream first tile into buffer 0 ----
    const int stride = gridDim.x;
    {
        int t0 = blockIdx.x;
        if (t0 < ntiles) {
            const float4* nsrc = (const float4*)neighbor + (size_t)t0 * 2048;
            #pragma unroll
            for (int i = 0; i < 8; ++i)
                cp16(sbase + SM_RAW0 + (uint32_t)(tid + i * NTHREADS) * 16, nsrc + tid + i * NTHREADS);
            if (tid < 128) cp16(sbase + SM_EX + (uint32_t)tid * 16, (const float4*)extra + (size_t)t0 * 128 + tid);
            if (tid < 16)  cp16(sbase + SM_WT + (uint32_t)tid * 16, (const float4*)nweight + (size_t)t0 * 16 + tid);
        }
        cp_commit();
    }

    // A ldsm lane addressing (rows within 64-row tile)
    const uint32_t afbase = sbase + SM_A
        + (uint32_t)((lane & 7) + ((lane >> 3) & 1) * 8) * ASTRIDE
        + (lane >> 4) * 16;

    const int g  = lane >> 2;
    const int i2 = (lane & 3) * 2;
    const int e0 = warp * 16 + i2;
    const float b00 = biass[e0],     b01 = biass[e0 + 1];
    const float b10 = biass[e0 + 8], b11 = biass[e0 + 9];
    const float v00 = w2s[e0],       v01 = w2s[e0 + 1];
    const float v10 = w2s[e0 + 8],   v11 = w2s[e0 + 9];

    int buf = 0;
    for (int tile = blockIdx.x; tile < ntiles; tile += stride) {
        cp_wait0();
        __syncthreads();   // raw[buf], ex[buf], wt[buf] ready

        const uint32_t rawb = sbase + (buf ? SM_RAW1 : SM_RAW0);
        const float* exb = (const float*)(smem + SM_EX + buf * 2048);
        const float* wtb = (const float*)(smem + SM_WT + buf * 256);

        // ---- build gated A tile (fp16, ldsm layout) from SMEM raw ----
        #pragma unroll
        for (int i = 0; i < 8; ++i) {
            int idx4 = tid + i * NTHREADS;      // 0..2047
            int m  = idx4 >> 5;                  // M row (bnl*16 + k), 0..63
            int q  = idx4 & 31;                  // float4 col
            float4 nv = *(const float4*)(smem + (rawb - sbase) + (uint32_t)idx4 * 16);
            float4 ev = *(const float4*)(exb + ((m >> 4) * 32 + q) * 4);
            uint2 hv;
            hv.x = pack_h2(nv.x * ev.x, nv.y * ev.y);
            hv.y = pack_h2(nv.z * ev.z, nv.w * ev.w);
            *(uint2*)(smem + SM_A + (uint32_t)m * ASTRIDE + (uint32_t)q * 8) = hv;
        }

        // ---- issue next tile's loads into other buffer (overlaps GEMM+output) ----
        {
            int nxt = tile + stride;
            if (nxt < ntiles) {
                const uint32_t dst = sbase + (buf ? SM_RAW0 : SM_RAW1);
                const float4* nsrc = (const float4*)neighbor + (size_t)nxt * 2048;
                #pragma unroll
                for (int i = 0; i < 8; ++i)
                    cp16(dst + (uint32_t)(tid + i * NTHREADS) * 16, nsrc + tid + i * NTHREADS);
                if (tid < 128) cp16(sbase + SM_EX + (buf ^ 1) * 2048 + (uint32_t)tid * 16,
                                    (const float4*)extra + (size_t)nxt * 128 + tid);
                if (tid < 16)  cp16(sbase + SM_WT + (buf ^ 1) * 256 + (uint32_t)tid * 16,
                                    (const float4*)nweight + (size_t)nxt * 16 + tid);
            }
            cp_commit();
        }
        __syncthreads();   // A tile ready

        // ---- GEMM: 4 m-tiles x warp's 16-e strip ----
        float c[4][2][4];
        #pragma unroll
        for (int mt = 0; mt < 4; ++mt)
            #pragma unroll
            for (int nt = 0; nt < 2; ++nt)
                { c[mt][nt][0]=0.f; c[mt][nt][1]=0.f; c[mt][nt][2]=0.f; c[mt][nt][3]=0.f; }

        #pragma unroll
        for (int kc = 0; kc < 8; ++kc) {
            #pragma unroll
            for (int mt = 0; mt < 4; ++mt) {
                uint32_t a0, a1, a2, a3;
                ldsm4(a0, a1, a2, a3, afbase + (uint32_t)(mt * 16) * ASTRIDE + kc * 32);
                mma_f16(c[mt][0][0], c[mt][0][1], c[mt][0][2], c[mt][0][3],
                        a0, a1, a2, a3, bb[kc][0], bb[kc][1]);
                mma_f16(c[mt][1][0], c[mt][1][1], c[mt][1][2], c[mt][1][3],
                        a0, a1, a2, a3, bb[kc][2], bb[kc][3]);
            }
        }

        // ---- partial w2-dot into SMEM ----
        #pragma unroll
        for (int mt = 0; mt < 4; ++mt) {
            const float wk0 = wtb[mt * 16 + g];
            const float wk1 = wtb[mt * 16 + g + 8];
            float p0 = leaky02(c[mt][0][0] + wk0 * b00) * v00
                     + leaky02(c[mt][0][1] + wk0 * b01) * v01
                     + leaky02(c[mt][1][0] + wk0 * b10) * v10
                     + leaky02(c[mt][1][1] + wk0 * b11) * v11;
            float p1 = leaky02(c[mt][0][2] + wk1 * b00) * v00
                     + leaky02(c[mt][0][3] + wk1 * b01) * v01
                     + leaky02(c[mt][1][2] + wk1 * b10) * v10
                     + leaky02(c[mt][1][3] + wk1 * b11) * v11;
            p0 += __shfl_xor_sync(0xffffffffu, p0, 1);
            p0 += __shfl_xor_sync(0xffffffffu, p0, 2);
            p1 += __shfl_xor_sync(0xffffffffu, p1, 1);
            p1 += __shfl_xor_sync(0xffffffffu, p1, 2);
            if ((lane & 3) == 0) {
                part[warp * 64 + mt * 16 + g]     = p0;
                part[warp * 64 + mt * 16 + g + 8] = p1;
            }
        }
        __syncthreads();   // partials ready

        // ---- warps 0-3: reduce, softmax, output bn0+warp (raw from SMEM) ----
        if (warp < TBN) {
            const int r = warp * 16 + (lane & 15);
            float s = 0.f;
            #pragma unroll
            for (int pw = 0; pw < 8; ++pw) s += part[pw * 64 + r];

            float mx = s;
            #pragma unroll
            for (int o = 8; o > 0; o >>= 1)
                mx = fmaxf(mx, __shfl_xor_sync(0xffffffffu, mx, o));
            float ev = __expf(s - mx);
            float es = ev;
            #pragma unroll
            for (int o = 8; o > 0; o >>= 1)
                es += __shfl_xor_sync(0xffffffffu, es, o);
            float alpha = ev / es;

            float al2[KN];
            #pragma unroll
            for (int k = 0; k < KN; ++k)
                al2[k] = __shfl_sync(0xffffffffu, alpha, k);

            float4 acc = make_float4(0.f, 0.f, 0.f, 0.f);
            #pragma unroll
            for (int k = 0; k < KN; ++k) {
                float4 nv = *(const float4*)(smem + (rawb - sbase)
                             + (uint32_t)((warp * 16 + k) * 32 + lane) * 16);
                acc.x = fmaf(al2[k], nv.x, acc.x);
                acc.y = fmaf(al2[k], nv.y, acc.y);
                acc.z = fmaf(al2[k], nv.z, acc.z);
                acc.w = fmaf(al2[k], nv.w, acc.w);
            }
            ((float4*)(out + ((size_t)tile * TBN + warp) * DIMX))[lane] = acc;
        }

        buf ^= 1;
        __syncthreads();   // raw[buf_old] reads done before anything rewrites state
    }
}

extern "C" void kernel_launch(void* const* d_in, const int* in_sizes, int n_in,
                              void* d_out, int out_size) {
    const float* neighbor = (const float*)d_in[1];
    const float* nweight  = (const float*)d_in[4];
    const float* extra    = (const float*)d_in[5];
    const float* w1       = (const float*)d_in[6];
    const float* w2       = (const float*)d_in[7];
    float* out            = (float*)d_out;

    const int total_bn = in_sizes[5] / DIMX;   // 65536
    const int ntiles   = total_bn / TBN;       // 16384

    cudaFuncSetAttribute(agg_mma_kernel, cudaFuncAttributeMaxDynamicSharedMemorySize, SM_TOTAL);
    agg_mma_kernel<<<304, NTHREADS, SM_TOTAL>>>(neighbor, nweight, extra, w1, w2, out, ntiles);
}

// round 13
// speedup vs baseline: 1.1348x; 1.0127x over previous
#include <cuda_runtime.h>
#include <cuda_fp16.h>
#include <cstdint>

// GlobalAggregator: B=256, N=256, K=16, DIM=128
// cp.async double-buffered pipeline. Tile = 4 bn (M=64 rows).
//  - B (w1^T fp16) fragments persistent in registers per warp (16-e strip, loaded once)
//  - raw neighbor/extra/nweight of tile t+1 streamed into SMEM via cp.async.cg while
//    tile t is gated->fp16-packed (A tile), GEMMed, and output
//  - output weighted-sum reads raw neighbor from SMEM (no global re-read)

#define DIMX 128
#define KN   16
#define TBN  4
#define MROWS 64
#define NTHREADS 256
#define ASTRIDE 272          // bytes per A/Bt row (128 fp16 + 8 pad)

#define SM_A     0           // 64 x 272 = 17408 (Bt spans here + RAW0 during init only)
#define SM_RAW0  17408       // 64x128 f32 = 32768
#define SM_RAW1  50176       // 32768
#define SM_EX    82944       // 2 x 512 f32 = 4096
#define SM_WT    87040       // 2 x 64 f32  = 512
#define SM_PART  87552       // 8 x 64 f32  = 2048
#define SM_BIAS  89600       // 128 f32
#define SM_W2    90112       // 128 f32
#define SM_TOTAL 90624

static __device__ __forceinline__ uint32_t smem_u32(const void* p) {
    uint32_t a;
    asm("{ .reg .u64 t; cvta.to.shared.u64 t, %1; cvt.u32.u64 %0, t; }" : "=r"(a) : "l"(p));
    return a;
}
static __device__ __forceinline__ void cp16(uint32_t saddr, const void* g) {
    asm volatile("cp.async.cg.shared.global [%0], [%1], 16;" :: "r"(saddr), "l"(g));
}
static __device__ __forceinline__ void cp_commit() {
    asm volatile("cp.async.commit_group;" ::: "memory");
}
static __device__ __forceinline__ void cp_wait0() {
    asm volatile("cp.async.wait_group 0;" ::: "memory");
}
static __device__ __forceinline__ void ldsm4(uint32_t& r0, uint32_t& r1, uint32_t& r2, uint32_t& r3,
                                             uint32_t addr) {
    asm volatile("ldmatrix.sync.aligned.m8n8.x4.shared.b16 {%0,%1,%2,%3}, [%4];"
                 : "=r"(r0), "=r"(r1), "=r"(r2), "=r"(r3) : "r"(addr));
}
static __device__ __forceinline__ void mma_f16(float& c0, float& c1, float& c2, float& c3,
                                               uint32_t a0, uint32_t a1, uint32_t a2, uint32_t a3,
                                               uint32_t b0, uint32_t b1) {
    asm volatile("mma.sync.aligned.m16n8k16.row.col.f32.f16.f16.f32 "
                 "{%0,%1,%2,%3},{%4,%5,%6,%7},{%8,%9},{%0,%1,%2,%3};"
                 : "+f"(c0), "+f"(c1), "+f"(c2), "+f"(c3)
                 : "r"(a0), "r"(a1), "r"(a2), "r"(a3), "r"(b0), "r"(b1));
}
static __device__ __forceinline__ uint32_t pack_h2(float x, float y) {
    __half2 h(__float2half_rn(x), __float2half_rn(y));
    return *(uint32_t*)&h;
}
__device__ __forceinline__ float leaky02(float v) { return v > 0.0f ? v : 0.2f * v; }

extern "C" __global__ void __launch_bounds__(NTHREADS, 2)
agg_mma_kernel(const float* __restrict__ neighbor,
               const float* __restrict__ nweight,
               const float* __restrict__ extra,
               const float* __restrict__ w1,
               const float* __restrict__ w2,
               float* __restrict__ out,
               int ntiles)
{
    extern __shared__ __align__(16) char smem[];
    const uint32_t sbase = smem_u32(smem);
    const int tid  = threadIdx.x;
    const int warp = tid >> 5;
    const int lane = tid & 31;

    float* part  = (float*)(smem + SM_PART);
    float* biass = (float*)(smem + SM_BIAS);
    float* w2s   = (float*)(smem + SM_W2);

    // ---- phase 0: build Bt (w1^T fp16) across SM_A+SM_RAW0 region (init only) ----
    for (int idx = tid; idx < DIMX * DIMX; idx += NTHREADS) {
        int d = idx >> 7;
        int e = idx & 127;
        *(__half*)(smem + (uint32_t)e * ASTRIDE + (uint32_t)d * 2) = __float2half_rn(w1[idx]);
    }
    if (tid < DIMX) {
        biass[tid] = w1[DIMX * DIMX + tid];
        w2s[tid]   = w2[tid];
    }
    __syncthreads();

    // ---- persistent B frags: warp's 16-e strip, 8 kc chunks (32 regs) ----
    uint32_t bb[8][4];
    {
        const uint32_t bfbase = sbase
            + (uint32_t)(warp * 16 + (lane & 7) + ((lane >> 4) & 1) * 8) * ASTRIDE
            + ((lane >> 3) & 1) * 16;
        #pragma unroll
        for (int kc = 0; kc < 8; ++kc)
            ldsm4(bb[kc][0], bb[kc][1], bb[kc][2], bb[kc][3], bfbase + kc * 32);
    }
    __syncthreads();   // Bt consumed; regions become A tile + raw buffers

    // ---- prologue: stream first tile into buffer 0 ----
    const int stride = gridDim.x;
    {
        int t0 = blockIdx.x;
        if (t0 < ntiles) {
            const float4* nsrc = (const float4*)neighbor + (size_t)t0 * 2048;
            #pragma unroll
            for (int i = 0; i < 8; ++i)
                cp16(sbase + SM_RAW0 + (uint32_t)(tid + i * NTHREADS) * 16, nsrc + tid + i * NTHREADS);
            if (tid < 128) cp16(sbase + SM_EX + (uint32_t)tid * 16, (const float4*)extra + (size_t)t0 * 128 + tid);
            if (tid < 16)  cp16(sbase + SM_WT + (uint32_t)tid * 16, (const float4*)nweight + (size_t)t0 * 16 + tid);
        }
        cp_commit();
    }

    // A ldsm lane addressing (rows within 64-row tile)
    const uint32_t afbase = sbase + SM_A
        + (uint32_t)((lane & 7) + ((lane >> 3) & 1) * 8) * ASTRIDE
        + (lane >> 4) * 16;

    const int g  = lane >> 2;
    const int i2 = (lane & 3) * 2;
    const int e0 = warp * 16 + i2;
    const float b00 = biass[e0],     b01 = biass[e0 + 1];
    const float b10 = biass[e0 + 8], b11 = biass[e0 + 9];
    const float v00 = w2s[e0],       v01 = w2s[e0 + 1];
    const float v10 = w2s[e0 + 8],   v11 = w2s[e0 + 9];

    int buf = 0;
    for (int tile = blockIdx.x; tile < ntiles; tile += stride) {
        cp_wait0();
        __syncthreads();   // raw[buf], ex[buf], wt[buf] ready

        const uint32_t rawb = sbase + (buf ? SM_RAW1 : SM_RAW0);
        const float* exb = (const float*)(smem + SM_EX + buf * 2048);
        const float* wtb = (const float*)(smem + SM_WT + buf * 256);

        // ---- build gated A tile (fp16, ldsm layout) from SMEM raw ----
        #pragma unroll
        for (int i = 0; i < 8; ++i) {
            int idx4 = tid + i * NTHREADS;      // 0..2047
            int m  = idx4 >> 5;                  // M row (bnl*16 + k), 0..63
            int q  = idx4 & 31;                  // float4 col
            float4 nv = *(const float4*)(smem + (rawb - sbase) + (uint32_t)idx4 * 16);
            float4 ev = *(const float4*)(exb + ((m >> 4) * 32 + q) * 4);
            uint2 hv;
            hv.x = pack_h2(nv.x * ev.x, nv.y * ev.y);
            hv.y = pack_h2(nv.z * ev.z, nv.w * ev.w);
            *(uint2*)(smem + SM_A + (uint32_t)m * ASTRIDE + (uint32_t)q * 8) = hv;
        }

        // ---- issue next tile's loads into other buffer (overlaps GEMM+output) ----
        {
            int nxt = tile + stride;
            if (nxt < ntiles) {
                const uint32_t dst = sbase + (buf ? SM_RAW0 : SM_RAW1);
                const float4* nsrc = (const float4*)neighbor + (size_t)nxt * 2048;
                #pragma unroll
                for (int i = 0; i < 8; ++i)
                    cp16(dst + (uint32_t)(tid + i * NTHREADS) * 16, nsrc + tid + i * NTHREADS);
                if (tid < 128) cp16(sbase + SM_EX + (buf ^ 1) * 2048 + (uint32_t)tid * 16,
                                    (const float4*)extra + (size_t)nxt * 128 + tid);
                if (tid < 16)  cp16(sbase + SM_WT + (buf ^ 1) * 256 + (uint32_t)tid * 16,
                                    (const float4*)nweight + (size_t)nxt * 16 + tid);
            }
            cp_commit();
        }
        __syncthreads();   // A tile ready

        // ---- GEMM: 4 m-tiles x warp's 16-e strip ----
        float c[4][2][4];
        #pragma unroll
        for (int mt = 0; mt < 4; ++mt)
            #pragma unroll
            for (int nt = 0; nt < 2; ++nt)
                { c[mt][nt][0]=0.f; c[mt][nt][1]=0.f; c[mt][nt][2]=0.f; c[mt][nt][3]=0.f; }

        #pragma unroll
        for (int kc = 0; kc < 8; ++kc) {
            #pragma unroll
            for (int mt = 0; mt < 4; ++mt) {
                uint32_t a0, a1, a2, a3;
                ldsm4(a0, a1, a2, a3, afbase + (uint32_t)(mt * 16) * ASTRIDE + kc * 32);
                mma_f16(c[mt][0][0], c[mt][0][1], c[mt][0][2], c[mt][0][3],
                        a0, a1, a2, a3, bb[kc][0], bb[kc][1]);
                mma_f16(c[mt][1][0], c[mt][1][1], c[mt][1][2], c[mt][1][3],
                        a0, a1, a2, a3, bb[kc][2], bb[kc][3]);
            }
        }

        // ---- partial w2-dot into SMEM ----
        #pragma unroll
        for (int mt = 0; mt < 4; ++mt) {
            const float wk0 = wtb[mt * 16 + g];
            const float wk1 = wtb[mt * 16 + g + 8];
            float p0 = leaky02(c[mt][0][0] + wk0 * b00) * v00
                     + leaky02(c[mt][0][1] + wk0 * b01) * v01
                     + leaky02(c[mt][1][0] + wk0 * b10) * v10
                     + leaky02(c[mt][1][1] + wk0 * b11) * v11;
            float p1 = leaky02(c[mt][0][2] + wk1 * b00) * v00
                     + leaky02(c[mt][0][3] + wk1 * b01) * v01
                     + leaky02(c[mt][1][2] + wk1 * b10) * v10
                     + leaky02(c[mt][1][3] + wk1 * b11) * v11;
            p0 += __shfl_xor_sync(0xffffffffu, p0, 1);
            p0 += __shfl_xor_sync(0xffffffffu, p0, 2);
            p1 += __shfl_xor_sync(0xffffffffu, p1, 1);
            p1 += __shfl_xor_sync(0xffffffffu, p1, 2);
            if ((lane & 3) == 0) {
                part[warp * 64 + mt * 16 + g]     = p0;
                part[warp * 64 + mt * 16 + g + 8] = p1;
            }
        }
        __syncthreads();   // partials ready

        // ---- warps 0-3: reduce, softmax, output bn0+warp (raw from SMEM) ----
        if (warp < TBN) {
            const int r = warp * 16 + (lane & 15);
            float s = 0.f;
            #pragma unroll
            for (int pw = 0; pw < 8; ++pw) s += part[pw * 64 + r];

            float mx = s;
            #pragma unroll
            for (int o = 8; o > 0; o >>= 1)
                mx = fmaxf(mx, __shfl_xor_sync(0xffffffffu, mx, o));
            float ev = __expf(s - mx);
            float es = ev;
            #pragma unroll
            for (int o = 8; o > 0; o >>= 1)
                es += __shfl_xor_sync(0xffffffffu, es, o);
            float alpha = ev / es;

            float al2[KN];
            #pragma unroll
            for (int k = 0; k < KN; ++k)
                al2[k] = __shfl_sync(0xffffffffu, alpha, k);

            float4 acc = make_float4(0.f, 0.f, 0.f, 0.f);
            #pragma unroll
            for (int k = 0; k < KN; ++k) {
                float4 nv = *(const float4*)(smem + (rawb - sbase)
                             + (uint32_t)((warp * 16 + k) * 32 + lane) * 16);
                acc.x = fmaf(al2[k], nv.x, acc.x);
                acc.y = fmaf(al2[k], nv.y, acc.y);
                acc.z = fmaf(al2[k], nv.z, acc.z);
                acc.w = fmaf(al2[k], nv.w, acc.w);
            }
            ((float4*)(out + ((size_t)tile * TBN + warp) * DIMX))[lane] = acc;
        }

        buf ^= 1;
        __syncthreads();   // raw[buf_old] reads done before anything rewrites state
    }
}

extern "C" void kernel_launch(void* const* d_in, const int* in_sizes, int n_in,
                              void* d_out, int out_size) {
    const float* neighbor = (const float*)d_in[1];
    const float* nweight  = (const float*)d_in[4];
    const float* extra    = (const float*)d_in[5];
    const float* w1       = (const float*)d_in[6];
    const float* w2       = (const float*)d_in[7];
    float* out            = (float*)d_out;

    const int total_bn = in_sizes[5] / DIMX;   // 65536
    const int ntiles   = total_bn / TBN;       // 16384

    cudaFuncSetAttribute(agg_mma_kernel, cudaFuncAttributeMaxDynamicSharedMemorySize, SM_TOTAL);
    agg_mma_kernel<<<304, NTHREADS, SM_TOTAL>>>(neighbor, nweight, extra, w1, w2, out, ntiles);
}